// round 2
// baseline (speedup 1.0000x reference)
#include <cuda_runtime.h>
#include <math.h>

#define S    8
#define NN   50000
#define EE   1600000
#define FIN  139
#define H    32
#define KK   600
#define LAT  65
#define C2L  296                  /* K/2 - 4 */
#define DENSE (C2L*32)            /* 9472 */
#define FEAT (LAT + DENSE)        /* 9537 */
#define LIN1_IN (FEAT*2)          /* 19074 */
#define SN   (S*NN)               /* 400000 */
#define SE   (S*EE)               /* 12800000 */

// ---------------- scratch (device globals; no allocation) ----------------
__device__ int   d_deg [SN];
__device__ float d_dinv[SN];
__device__ float d_g   [SN*H];     // per-layer transformed+dinv-scaled features
__device__ float d_acc [SN*H];     // aggregation accumulator (init = g covers self loop)
__device__ float d_h1  [SN*H];
__device__ float d_h2  [SN*H];
__device__ float d_g2  [SN];
__device__ float d_acc2[SN];
__device__ float d_h3  [SN];
__device__ float d_feats[S*FEAT];
__device__ int   d_topk[S*KK];
__device__ float d_l1  [128];

// ---------------- init: deg = 1 (self loop), l1 acc = bias ----------------
__global__ void k_init(const float* __restrict__ l1b) {
    int i = blockIdx.x*blockDim.x + threadIdx.x;
    if (i < SN)  d_deg[i] = 1;
    if (i < 128) d_l1[i]  = l1b[i];
}

// ---------------- in-degree ----------------
__global__ void k_deg(const int* __restrict__ ei) {
    int gid = blockIdx.x*blockDim.x + threadIdx.x;
    if (gid >= SE) return;
    int s = gid / EE, e = gid - s*EE;
    int dst = __ldg(ei + (size_t)s*2*EE + EE + e);
    atomicAdd(&d_deg[s*NN + dst], 1);
}

__global__ void k_dinv() {
    int i = blockIdx.x*blockDim.x + threadIdx.x;
    if (i < SN) d_dinv[i] = rsqrtf((float)d_deg[i]);
}

// ---------------- layer-1 GEMM: g = (x @ W0) * dinv ; acc = g ----------------
__global__ void __launch_bounds__(256) k_gemm0(const float* __restrict__ x,
                                               const float* __restrict__ W0) {
    __shared__ float W0s[FIN*H];
    __shared__ float xs[32][FIN];
    int tid = threadIdx.x;
    int g0  = blockIdx.x * 32;
    for (int i = tid; i < FIN*H; i += 256) W0s[i] = W0[i];
    const float* xg = x + (size_t)g0*FIN;
    for (int i = tid; i < 32*FIN; i += 256) { int r = i/FIN; xs[r][i - r*FIN] = xg[i]; }
    __syncthreads();
    int f = tid & 31, nb = (tid >> 5) * 4;
    float a0=0.f, a1=0.f, a2=0.f, a3=0.f;
    #pragma unroll 1
    for (int k = 0; k < FIN; k++) {
        float w = W0s[k*H + f];
        a0 = fmaf(xs[nb+0][k], w, a0);
        a1 = fmaf(xs[nb+1][k], w, a1);
        a2 = fmaf(xs[nb+2][k], w, a2);
        a3 = fmaf(xs[nb+3][k], w, a3);
    }
    int gA = g0 + nb;
    float r0 = a0 * d_dinv[gA+0];
    float r1 = a1 * d_dinv[gA+1];
    float r2 = a2 * d_dinv[gA+2];
    float r3 = a3 * d_dinv[gA+3];
    d_g[(size_t)(gA+0)*H+f]=r0; d_acc[(size_t)(gA+0)*H+f]=r0;
    d_g[(size_t)(gA+1)*H+f]=r1; d_acc[(size_t)(gA+1)*H+f]=r1;
    d_g[(size_t)(gA+2)*H+f]=r2; d_acc[(size_t)(gA+2)*H+f]=r2;
    d_g[(size_t)(gA+3)*H+f]=r3; d_acc[(size_t)(gA+3)*H+f]=r3;
}

// ---------------- edge scatter for 32-feature layers (scalar atomics) ----------------
__global__ void __launch_bounds__(256) k_edge32(const int* __restrict__ ei) {
    int gid = blockIdx.x*blockDim.x + threadIdx.x;   // SE*8
    int c  = gid & 7;
    int ea = gid >> 3;
    int s = ea / EE, e = ea - s*EE;
    const int* eb = ei + (size_t)s*2*EE;
    int src = __ldg(eb + e);
    int dst = __ldg(eb + EE + e);
    float4 v = *(const float4*)(d_g + (size_t)(s*NN+src)*H + c*4);
    float* a = d_acc + (size_t)(s*NN+dst)*H + c*4;
    atomicAdd(a+0, v.x);
    atomicAdd(a+1, v.y);
    atomicAdd(a+2, v.z);
    atomicAdd(a+3, v.w);
}

// ---------------- h1 = tanh(acc*dinv + b0); g = (h1 @ W1)*dinv ; acc = g ----------------
__global__ void __launch_bounds__(256) k_hg1(const float* __restrict__ b0,
                                             const float* __restrict__ W1) {
    __shared__ float W1s[H*H];
    int tid = threadIdx.x;
    for (int i = tid; i < H*H; i += 256) W1s[i] = W1[i];
    __syncthreads();
    int g = blockIdx.x*8 + (tid >> 5);
    int f = tid & 31;
    float dv = d_dinv[g];
    float h  = tanhf(d_acc[(size_t)g*H+f]*dv + __ldg(b0+f));
    d_h1[(size_t)g*H+f] = h;
    float v = 0.f;
    #pragma unroll
    for (int k = 0; k < H; k++)
        v = fmaf(__shfl_sync(0xffffffffu, h, k), W1s[k*H+f], v);
    v *= dv;
    d_g[(size_t)g*H+f]   = v;
    d_acc[(size_t)g*H+f] = v;
}

// ---------------- h2 = tanh(acc*dinv + b1); g2 = (h2 . W2)*dinv (scalar) ----------------
__global__ void __launch_bounds__(256) k_hg2(const float* __restrict__ b1,
                                             const float* __restrict__ W2) {
    int tid = threadIdx.x;
    int g = blockIdx.x*8 + (tid >> 5);
    int f = tid & 31;
    float dv = d_dinv[g];
    float h  = tanhf(d_acc[(size_t)g*H+f]*dv + __ldg(b1+f));
    d_h2[(size_t)g*H+f] = h;
    float p = h * __ldg(W2 + f);
    #pragma unroll
    for (int o = 16; o > 0; o >>= 1) p += __shfl_xor_sync(0xffffffffu, p, o);
    if (f == 0) { float gv = p*dv; d_g2[g] = gv; d_acc2[g] = gv; }
}

// ---------------- scalar edge scatter (layer 3) ----------------
__global__ void __launch_bounds__(256) k_edge3(const int* __restrict__ ei) {
    int gid = blockIdx.x*blockDim.x + threadIdx.x;
    if (gid >= SE) return;
    int s = gid / EE, e = gid - s*EE;
    const int* eb = ei + (size_t)s*2*EE;
    int src = __ldg(eb + e);
    int dst = __ldg(eb + EE + e);
    atomicAdd(&d_acc2[s*NN + dst], d_g2[s*NN + src]);
}

__global__ void k_h3(const float* __restrict__ b2) {
    int i = blockIdx.x*blockDim.x + threadIdx.x;
    if (i < SN) d_h3[i] = tanhf(d_acc2[i]*d_dinv[i] + __ldg(b2));
}

// ---------------- exact stable top-600 per snapshot ----------------
__device__ __forceinline__ unsigned mono_f(float v) {
    unsigned u = __float_as_uint(v);
    return (u & 0x80000000u) ? ~u : (u | 0x80000000u);
}

__global__ void k_topk() {
    extern __shared__ unsigned char smraw[];
    int* hist = (int*)smraw;                                   // 4096 ints
    unsigned long long* cand = (unsigned long long*)(smraw + 4096*4); // 8192 u64
    __shared__ int sB1, sPre, sB2, sCnt;
    int s = blockIdx.x, tid = threadIdx.x;
    const float* key = d_h3 + s*NN;

    for (int i = tid; i < 4096; i += 1024) hist[i] = 0;
    __syncthreads();
    for (int n = tid; n < NN; n += 1024)
        atomicAdd(&hist[mono_f(key[n]) >> 20], 1);
    __syncthreads();
    if (tid == 0) {
        int cum = 0, b = 4095;
        for (; b >= 0; b--) { cum += hist[b]; if (cum >= KK) break; }
        sB1 = b; sPre = cum - hist[b];
    }
    __syncthreads();
    int B1 = sB1, pre1 = sPre;
    for (int i = tid; i < 4096; i += 1024) hist[i] = 0;
    __syncthreads();
    for (int n = tid; n < NN; n += 1024) {
        unsigned u = mono_f(key[n]);
        if ((int)(u >> 20) == B1) atomicAdd(&hist[(u >> 8) & 0xFFF], 1);
    }
    __syncthreads();
    if (tid == 0) {
        int cum = pre1, b = 4095;
        for (; b >= 0; b--) { cum += hist[b]; if (cum >= KK) break; }
        sB2 = b; sCnt = 0;
    }
    __syncthreads();
    unsigned T = ((unsigned)B1 << 12) | (unsigned)sB2;   // top-24-bit threshold
    for (int n = tid; n < NN; n += 1024) {
        unsigned u = mono_f(key[n]);
        if ((u >> 8) >= T) {
            int p = atomicAdd(&sCnt, 1);
            if (p < 8192)
                cand[p] = ((unsigned long long)u << 32) | (unsigned)(0xFFFFFFFFu - n);
        }
    }
    __syncthreads();
    int cnt = sCnt < 8192 ? sCnt : 8192;
    for (int i = tid; i < 8192; i += 1024) if (i >= cnt) cand[i] = 0ull;
    __syncthreads();
    // bitonic sort, descending
    for (int k = 2; k <= 8192; k <<= 1) {
        for (int j = k >> 1; j > 0; j >>= 1) {
            for (int t = tid; t < 8192; t += 1024) {
                int ixj = t ^ j;
                if (ixj > t) {
                    unsigned long long a = cand[t], b = cand[ixj];
                    bool up = ((t & k) == 0);            // descending blocks
                    if (up ? (a < b) : (a > b)) { cand[t] = b; cand[ixj] = a; }
                }
            }
            __syncthreads();
        }
    }
    for (int j = tid; j < KK; j += 1024)
        d_topk[s*KK + j] = (int)(0xFFFFFFFFu - (unsigned)(cand[j] & 0xFFFFFFFFu));
}

// ---------------- sort-pool convs + emb_edge ----------------
__global__ void k_pool(const float* __restrict__ c1w, const float* __restrict__ c1b,
                       const float* __restrict__ c2w, const float* __restrict__ c2b) {
    extern __shared__ float smf[];
    float* z1  = smf;            // 16*600
    float* zp  = z1 + 16*600;    // 16*300
    float* w1s = zp + 16*300;    // 16*65
    float* w2s = w1s + 16*65;    // 32*16*5
    int s = blockIdx.x, tid = threadIdx.x;
    for (int i = tid; i < 16*65;   i += 1024) w1s[i] = c1w[i];
    for (int i = tid; i < 32*16*5; i += 1024) w2s[i] = c2w[i];
    __syncthreads();
    for (int p = tid; p < 16*600; p += 1024) {
        int c = p / 600, j = p - c*600;
        int n = d_topk[s*KK + j];
        int base = s*NN + n;
        const float* w  = w1s + c*65;
        const float* r1 = d_h1 + (size_t)base*H;
        const float* r2 = d_h2 + (size_t)base*H;
        float a = __ldg(c1b + c);
        #pragma unroll 8
        for (int t = 0; t < 32; t++) a = fmaf(w[t],    r1[t], a);
        #pragma unroll 8
        for (int t = 0; t < 32; t++) a = fmaf(w[32+t], r2[t], a);
        a = fmaf(w[64], d_h3[base], a);
        z1[c*600 + j] = fmaxf(a, 0.f);
    }
    __syncthreads();
    for (int p = tid; p < 16*300; p += 1024) {
        int c = p / 300, j = p - c*300;
        zp[c*300 + j] = fmaxf(z1[c*600 + 2*j], z1[c*600 + 2*j + 1]);
    }
    __syncthreads();
    float* out = d_feats + s*FEAT;
    for (int p = tid; p < 32*C2L; p += 1024) {
        int o = p / C2L, j = p - o*C2L;
        float a = __ldg(c2b + o);
        #pragma unroll
        for (int i = 0; i < 16; i++) {
            const float* w = w2s + (o*16 + i)*5;
            const float* z = zp + i*300 + j;
            #pragma unroll
            for (int t = 0; t < 5; t++) a = fmaf(w[t], z[t], a);
        }
        out[LAT + p] = fmaxf(a, 0.f);
    }
    for (int t = tid; t < LAT; t += 1024) {
        int b0i = s*NN, b1i = s*NN + 1;
        float v0 = (t < 32) ? d_h1[(size_t)b0i*H + t] : (t < 64) ? d_h2[(size_t)b0i*H + (t-32)] : d_h3[b0i];
        float v1 = (t < 32) ? d_h1[(size_t)b1i*H + t] : (t < 64) ? d_h2[(size_t)b1i*H + (t-32)] : d_h3[b1i];
        out[t] = v0 * v1;
    }
}

// ---------------- temporal combine + lin1 GEMV ----------------
__global__ void __launch_bounds__(128) k_final1(const float* __restrict__ wp,
                                                const float* __restrict__ l1W) {
    __shared__ float inp[64];
    int tid = threadIdx.x, i0 = blockIdx.x*64;
    float om = 1.0f - *wp;
    if (tid < 64) {
        int i = i0 + tid; float v = 0.f;
        if (i < LIN1_IN) {
            if (i < FEAT) {
                v = d_feats[6*FEAT + i];
                float coef = 1.f;
                for (int t = 5; t >= 0; t--) { v = fmaf(coef, d_feats[t*FEAT + i], v); coef *= om; }
            } else v = d_feats[7*FEAT + (i - FEAT)];
        }
        inp[tid] = v;
    }
    __syncthreads();
    int lim = LIN1_IN - i0; if (lim > 64) lim = 64;
    float part = 0.f;
    for (int l = 0; l < lim; l++)
        part = fmaf(inp[l], l1W[(size_t)(i0 + l)*128 + tid], part);
    atomicAdd(&d_l1[tid], part);
}

__global__ void k_final2(const float* __restrict__ l4W, const float* __restrict__ l4b,
                         float* __restrict__ out) {
    __shared__ float red[4];
    int tid = threadIdx.x;                      // 128
    float h = fmaxf(d_l1[tid], 0.f);
    float p = h * l4W[tid];
    #pragma unroll
    for (int o = 16; o > 0; o >>= 1) p += __shfl_xor_sync(0xffffffffu, p, o);
    if ((tid & 31) == 0) red[tid >> 5] = p;
    __syncthreads();
    if (tid == 0) out[0] = red[0] + red[1] + red[2] + red[3] + l4b[0];
}

// ---------------- launch ----------------
extern "C" void kernel_launch(void* const* d_in, const int* in_sizes, int n_in,
                              void* d_out, int out_size) {
    // --- robust input mapping: resolve by size signature ---
    // dict order (w/ batch):  x, ei, batch, W0,b0,W1,b1,W2,b2, c1w,c1b,c2w,c2b, w, l1W,l1b,l4W,l4b
    // dict order (no batch):  x, ei,        W0,b0,...
    // alphabetical:           W0,W1,W2,b0,b1,b2,batch,c1b,c1w,c2b,c2w, ei, l1W,l1b,l4W,l4b, w, x
    int iX, iEI, iW0, iB0, iW1, iB1, iW2, iB2, iC1W, iC1B, iC2W, iC2B, iW, iL1W, iL1B, iL4W, iL4B;
    if (in_sizes[0] == SN*FIN || in_sizes[0] == 2*SE) {
        // dict order (possibly x/ei swapped)
        if (in_sizes[0] == SN*FIN) { iX = 0; iEI = 1; } else { iX = 1; iEI = 0; }
        int b = (n_in >= 3 && in_sizes[2] == NN) ? 3 : 2;   // skip batch if present
        iW0 = b;    iB0 = b+1;  iW1 = b+2;  iB1 = b+3;  iW2 = b+4;  iB2 = b+5;
        iC1W = b+6; iC1B = b+7; iC2W = b+8; iC2B = b+9; iW = b+10;
        iL1W = b+11; iL1B = b+12; iL4W = b+13; iL4B = b+14;
    } else {
        // alphabetical order
        iW0 = 0; iW1 = 1; iW2 = 2; iB0 = 3; iB1 = 4; iB2 = 5;
        iC1B = 7; iC1W = 8; iC2B = 9; iC2W = 10; iEI = 11;
        iL1W = 12; iL1B = 13; iL4W = 14; iL4B = 15; iW = 16; iX = 17;
    }

    const float* x   = (const float*)d_in[iX];
    const int*   ei  = (const int*)  d_in[iEI];
    const float* W0  = (const float*)d_in[iW0];
    const float* b0  = (const float*)d_in[iB0];
    const float* W1  = (const float*)d_in[iW1];
    const float* b1  = (const float*)d_in[iB1];
    const float* W2  = (const float*)d_in[iW2];
    const float* b2  = (const float*)d_in[iB2];
    const float* c1w = (const float*)d_in[iC1W];
    const float* c1b = (const float*)d_in[iC1B];
    const float* c2w = (const float*)d_in[iC2W];
    const float* c2b = (const float*)d_in[iC2B];
    const float* wp  = (const float*)d_in[iW];
    const float* l1W = (const float*)d_in[iL1W];
    const float* l1b = (const float*)d_in[iL1B];
    const float* l4W = (const float*)d_in[iL4W];
    const float* l4b = (const float*)d_in[iL4B];
    float* out = (float*)d_out;

    cudaFuncSetAttribute(k_topk, cudaFuncAttributeMaxDynamicSharedMemorySize, 4096*4 + 8192*8);
    cudaFuncSetAttribute(k_pool, cudaFuncAttributeMaxDynamicSharedMemorySize,
                         (16*600 + 16*300 + 16*65 + 32*16*5) * 4);

    k_init<<<(SN + 255)/256, 256>>>(l1b);
    k_deg <<<(SE + 255)/256, 256>>>(ei);
    k_dinv<<<(SN + 255)/256, 256>>>();
    k_gemm0<<<SN/32, 256>>>(x, W0);
    k_edge32<<<(SE*8)/256, 256>>>(ei);          // layer 1 scatter
    k_hg1<<<SN/8, 256>>>(b0, W1);
    k_edge32<<<(SE*8)/256, 256>>>(ei);          // layer 2 scatter
    k_hg2<<<SN/8, 256>>>(b1, W2);
    k_edge3<<<(SE + 255)/256, 256>>>(ei);       // layer 3 scatter (scalar)
    k_h3<<<(SN + 255)/256, 256>>>(b2);
    k_topk<<<S, 1024, 4096*4 + 8192*8>>>();
    k_pool<<<S, 1024, (16*600 + 16*300 + 16*65 + 32*16*5)*4>>>(c1w, c1b, c2w, c2b);
    k_final1<<<(LIN1_IN + 63)/64, 128>>>(wp, l1W);
    k_final2<<<1, 128>>>(l4W, l4b, out);
}

// round 9
// speedup vs baseline: 1.6827x; 1.6827x over previous
#include <cuda_runtime.h>
#include <math.h>

#define S    8
#define NN   50000
#define EE   1600000
#define FIN  139
#define H    32
#define KK   600
#define LAT  65
#define C2L  296
#define DENSE (C2L*32)
#define FEAT (LAT + DENSE)
#define LIN1_IN (FEAT*2)
#define SN   (S*NN)               /* 400000 */
#define SE   (S*EE)               /* 12800000 */
#define NCHUNK ((SN + 511) / 512) /* 782 */

// ---------------- scratch ----------------
__device__ int   d_deg [SN];
__device__ float d_dinv[SN];
__device__ float d_g   [SN*H];
__device__ float d_gB  [SN*H];
__device__ float d_h1  [SN*H];
__device__ float d_h2  [SN*H];
__device__ float d_g2  [SN];
__device__ float d_h3  [SN];
__device__ int   d_off [SN];
__device__ int   d_cursor[SN];
__device__ int   d_bsum[1024];
__device__ int   d_csr [SE];
__device__ float d_feats[S*FEAT];
__device__ int   d_topk[S*KK];
__device__ float d_l1  [128];

// ---------------- init ----------------
__global__ void k_init(const float* __restrict__ l1b) {
    int i = blockIdx.x*blockDim.x + threadIdx.x;
    if (i < SN)  d_deg[i] = 1;
    if (i < 128) d_l1[i]  = l1b[i];
}

__global__ void k_deg(const int* __restrict__ ei) {
    int gid = blockIdx.x*blockDim.x + threadIdx.x;
    if (gid >= SE) return;
    int s = gid / EE, e = gid - s*EE;
    int dst = __ldg(ei + (size_t)s*2*EE + EE + e);
    atomicAdd(&d_deg[s*NN + dst], 1);
}

__global__ void k_dinv() {
    int i = blockIdx.x*blockDim.x + threadIdx.x;
    if (i < SN) d_dinv[i] = rsqrtf((float)d_deg[i]);
}

// ---------------- CSR build ----------------
__global__ void k_scanA() {
    __shared__ int sh[512];
    int tid = threadIdx.x;
    int i = blockIdx.x*512 + tid;
    int v = (i < SN) ? d_deg[i]-1 : 0;
    sh[tid] = v; __syncthreads();
    for (int o = 1; o < 512; o <<= 1) {
        int t = (tid >= o) ? sh[tid-o] : 0;
        __syncthreads(); sh[tid] += t; __syncthreads();
    }
    if (i < SN) d_off[i] = sh[tid] - v;
    if (tid == 511) d_bsum[blockIdx.x] = sh[511];
}

__global__ void k_scanB() {
    __shared__ int sh[1024];
    int tid = threadIdx.x;
    int v = (tid < NCHUNK) ? d_bsum[tid] : 0;
    sh[tid] = v; __syncthreads();
    for (int o = 1; o < 1024; o <<= 1) {
        int t = (tid >= o) ? sh[tid-o] : 0;
        __syncthreads(); sh[tid] += t; __syncthreads();
    }
    if (tid < NCHUNK) d_bsum[tid] = sh[tid] - v;
}

__global__ void k_scanC() {
    int i = blockIdx.x*blockDim.x + threadIdx.x;
    if (i >= SN) return;
    int o = d_off[i] + d_bsum[i >> 9];
    d_off[i] = o;
    d_cursor[i] = o;
}

__global__ void k_fill(const int* __restrict__ ei) {
    int gid = blockIdx.x*blockDim.x + threadIdx.x;
    if (gid >= SE) return;
    int s = gid / EE, e = gid - s*EE;
    const int* eb = ei + (size_t)s*2*EE;
    int src = __ldg(eb + e);
    int dst = __ldg(eb + EE + e);
    int pos = atomicAdd(&d_cursor[s*NN + dst], 1);
    d_csr[pos] = s*NN + src;
}

// ---------------- layer-1 GEMM (R2-proven version) ----------------
__global__ void __launch_bounds__(256) k_gemm0(const float* __restrict__ x,
                                               const float* __restrict__ W0) {
    __shared__ float W0s[FIN*H];
    __shared__ float xs[32][FIN];
    int tid = threadIdx.x;
    int g0  = blockIdx.x * 32;
    for (int i = tid; i < FIN*H; i += 256) W0s[i] = W0[i];
    const float* xg = x + (size_t)g0*FIN;
    for (int i = tid; i < 32*FIN; i += 256) { int r = i/FIN; xs[r][i - r*FIN] = xg[i]; }
    __syncthreads();
    int f = tid & 31, nb = (tid >> 5) * 4;
    float a0=0.f, a1=0.f, a2=0.f, a3=0.f;
    #pragma unroll 1
    for (int k = 0; k < FIN; k++) {
        float w = W0s[k*H + f];
        a0 = fmaf(xs[nb+0][k], w, a0);
        a1 = fmaf(xs[nb+1][k], w, a1);
        a2 = fmaf(xs[nb+2][k], w, a2);
        a3 = fmaf(xs[nb+3][k], w, a3);
    }
    int gA = g0 + nb;
    d_g[(size_t)(gA+0)*H+f] = a0 * d_dinv[gA+0];
    d_g[(size_t)(gA+1)*H+f] = a1 * d_dinv[gA+1];
    d_g[(size_t)(gA+2)*H+f] = a2 * d_dinv[gA+2];
    d_g[(size_t)(gA+3)*H+f] = a3 * d_dinv[gA+3];
}

// ---------------- simple broadcast gather: warp-per-node, lane=feature ----------------
__device__ __forceinline__ float gatherS(const float* __restrict__ gsrc, int n, int f) {
    int off = d_off[n];
    int end = off + d_deg[n] - 1;
    float a0 = gsrc[(size_t)n*H + f];   // self loop
    float a1 = 0.f, a2 = 0.f, a3 = 0.f;
    int e = off;
    for (; e + 4 <= end; e += 4) {
        int i0 = __ldg(d_csr + e);
        int i1 = __ldg(d_csr + e + 1);
        int i2 = __ldg(d_csr + e + 2);
        int i3 = __ldg(d_csr + e + 3);
        a0 += gsrc[(size_t)i0*H + f];
        a1 += gsrc[(size_t)i1*H + f];
        a2 += gsrc[(size_t)i2*H + f];
        a3 += gsrc[(size_t)i3*H + f];
    }
    for (; e < end; e++)
        a0 += gsrc[(size_t)__ldg(d_csr + e)*H + f];
    return (a0 + a1) + (a2 + a3);
}

// ---------------- fused: agg(g) -> h1 -> gB ----------------
__global__ void __launch_bounds__(256) k_l1(const float* __restrict__ b0,
                                            const float* __restrict__ W1) {
    __shared__ float W1s[H*H];
    int tid = threadIdx.x;
    for (int i = tid; i < H*H; i += 256) W1s[i] = W1[i];
    __syncthreads();
    int n = blockIdx.x*8 + (tid >> 5);
    int f = tid & 31;
    float acc = gatherS(d_g, n, f);
    float dv = d_dinv[n];
    float h = tanhf(acc*dv + __ldg(b0 + f));
    d_h1[(size_t)n*H + f] = h;
    float v = 0.f;
    #pragma unroll
    for (int k = 0; k < H; k++)
        v = fmaf(__shfl_sync(0xffffffffu, h, k), W1s[k*H + f], v);
    d_gB[(size_t)n*H + f] = v * dv;
}

// ---------------- fused: agg(gB) -> h2 -> g2 ----------------
__global__ void __launch_bounds__(256) k_l2(const float* __restrict__ b1,
                                            const float* __restrict__ W2) {
    int tid = threadIdx.x;
    int n = blockIdx.x*8 + (tid >> 5);
    int f = tid & 31;
    float acc = gatherS(d_gB, n, f);
    float dv = d_dinv[n];
    float h = tanhf(acc*dv + __ldg(b1 + f));
    d_h2[(size_t)n*H + f] = h;
    float p = h * __ldg(W2 + f);
    #pragma unroll
    for (int o = 16; o > 0; o >>= 1) p += __shfl_xor_sync(0xffffffffu, p, o);
    if (f == 0) d_g2[n] = p * dv;
}

// ---------------- fused: scalar agg(g2) -> h3 ----------------
__global__ void __launch_bounds__(256) k_l3(const float* __restrict__ b2) {
    int tid = threadIdx.x;
    int n = blockIdx.x*8 + (tid >> 5);
    int lane = tid & 31;
    int off = d_off[n];
    int cnt = d_deg[n] - 1;
    float a = 0.f;
    for (int e = lane; e < cnt; e += 32) a += d_g2[d_csr[off + e]];
    #pragma unroll
    for (int o = 16; o > 0; o >>= 1) a += __shfl_xor_sync(0xffffffffu, a, o);
    if (lane == 0)
        d_h3[n] = tanhf((d_g2[n] + a) * d_dinv[n] + __ldg(b2));
}

// ---------------- exact stable top-600 per snapshot ----------------
__device__ __forceinline__ unsigned mono_f(float v) {
    unsigned u = __float_as_uint(v);
    return (u & 0x80000000u) ? ~u : (u | 0x80000000u);
}

__global__ void k_topk() {
    extern __shared__ unsigned char smraw[];
    int* hist = (int*)smraw;
    unsigned long long* cand = (unsigned long long*)(smraw + 4096*4);
    __shared__ int sB1, sPre, sB2, sCnt;
    int s = blockIdx.x, tid = threadIdx.x;
    const float* key = d_h3 + s*NN;

    for (int i = tid; i < 4096; i += 1024) hist[i] = 0;
    __syncthreads();
    for (int n = tid; n < NN; n += 1024)
        atomicAdd(&hist[mono_f(key[n]) >> 20], 1);
    __syncthreads();
    if (tid == 0) {
        int cum = 0, b = 4095;
        for (; b >= 0; b--) { cum += hist[b]; if (cum >= KK) break; }
        sB1 = b; sPre = cum - hist[b];
    }
    __syncthreads();
    int B1 = sB1, pre1 = sPre;
    for (int i = tid; i < 4096; i += 1024) hist[i] = 0;
    __syncthreads();
    for (int n = tid; n < NN; n += 1024) {
        unsigned u = mono_f(key[n]);
        if ((int)(u >> 20) == B1) atomicAdd(&hist[(u >> 8) & 0xFFF], 1);
    }
    __syncthreads();
    if (tid == 0) {
        int cum = pre1, b = 4095;
        for (; b >= 0; b--) { cum += hist[b]; if (cum >= KK) break; }
        sB2 = b; sCnt = 0;
    }
    __syncthreads();
    unsigned T = ((unsigned)B1 << 12) | (unsigned)sB2;
    for (int n = tid; n < NN; n += 1024) {
        unsigned u = mono_f(key[n]);
        if ((u >> 8) >= T) {
            int p = atomicAdd(&sCnt, 1);
            if (p < 8192)
                cand[p] = ((unsigned long long)u << 32) | (unsigned)(0xFFFFFFFFu - n);
        }
    }
    __syncthreads();
    int cnt = sCnt < 8192 ? sCnt : 8192;
    for (int i = tid; i < 8192; i += 1024) if (i >= cnt) cand[i] = 0ull;
    __syncthreads();
    for (int k = 2; k <= 8192; k <<= 1) {
        for (int j = k >> 1; j > 0; j >>= 1) {
            for (int t = tid; t < 8192; t += 1024) {
                int ixj = t ^ j;
                if (ixj > t) {
                    unsigned long long a = cand[t], b = cand[ixj];
                    bool up = ((t & k) == 0);
                    if (up ? (a < b) : (a > b)) { cand[t] = b; cand[ixj] = a; }
                }
            }
            __syncthreads();
        }
    }
    for (int j = tid; j < KK; j += 1024)
        d_topk[s*KK + j] = (int)(0xFFFFFFFFu - (unsigned)(cand[j] & 0xFFFFFFFFu));
}

// ---------------- sort-pool convs + emb_edge ----------------
__global__ void k_pool(const float* __restrict__ c1w, const float* __restrict__ c1b,
                       const float* __restrict__ c2w, const float* __restrict__ c2b) {
    extern __shared__ float smf[];
    float* z1  = smf;
    float* zp  = z1 + 16*600;
    float* w1s = zp + 16*300;
    float* w2s = w1s + 16*65;
    int s = blockIdx.x, tid = threadIdx.x;
    for (int i = tid; i < 16*65;   i += 1024) w1s[i] = c1w[i];
    for (int i = tid; i < 32*16*5; i += 1024) w2s[i] = c2w[i];
    __syncthreads();
    for (int p = tid; p < 16*600; p += 1024) {
        int c = p / 600, j = p - c*600;
        int n = d_topk[s*KK + j];
        int base = s*NN + n;
        const float* w  = w1s + c*65;
        const float* r1 = d_h1 + (size_t)base*H;
        const float* r2 = d_h2 + (size_t)base*H;
        float a = __ldg(c1b + c);
        #pragma unroll 8
        for (int t = 0; t < 32; t++) a = fmaf(w[t],    r1[t], a);
        #pragma unroll 8
        for (int t = 0; t < 32; t++) a = fmaf(w[32+t], r2[t], a);
        a = fmaf(w[64], d_h3[base], a);
        z1[c*600 + j] = fmaxf(a, 0.f);
    }
    __syncthreads();
    for (int p = tid; p < 16*300; p += 1024) {
        int c = p / 300, j = p - c*300;
        zp[c*300 + j] = fmaxf(z1[c*600 + 2*j], z1[c*600 + 2*j + 1]);
    }
    __syncthreads();
    float* out = d_feats + s*FEAT;
    for (int p = tid; p < 32*C2L; p += 1024) {
        int o = p / C2L, j = p - o*C2L;
        float a = __ldg(c2b + o);
        #pragma unroll
        for (int i = 0; i < 16; i++) {
            const float* w = w2s + (o*16 + i)*5;
            const float* z = zp + i*300 + j;
            #pragma unroll
            for (int t = 0; t < 5; t++) a = fmaf(w[t], z[t], a);
        }
        out[LAT + p] = fmaxf(a, 0.f);
    }
    for (int t = tid; t < LAT; t += 1024) {
        int b0i = s*NN, b1i = s*NN + 1;
        float v0 = (t < 32) ? d_h1[(size_t)b0i*H + t] : (t < 64) ? d_h2[(size_t)b0i*H + (t-32)] : d_h3[b0i];
        float v1 = (t < 32) ? d_h1[(size_t)b1i*H + t] : (t < 64) ? d_h2[(size_t)b1i*H + (t-32)] : d_h3[b1i];
        out[t] = v0 * v1;
    }
}

// ---------------- temporal combine + lin1 GEMV ----------------
__global__ void __launch_bounds__(128) k_final1(const float* __restrict__ wp,
                                                const float* __restrict__ l1W) {
    __shared__ float inp[64];
    int tid = threadIdx.x, i0 = blockIdx.x*64;
    float om = 1.0f - *wp;
    if (tid < 64) {
        int i = i0 + tid; float v = 0.f;
        if (i < LIN1_IN) {
            if (i < FEAT) {
                v = d_feats[6*FEAT + i];
                float coef = 1.f;
                for (int t = 5; t >= 0; t--) { v = fmaf(coef, d_feats[t*FEAT + i], v); coef *= om; }
            } else v = d_feats[7*FEAT + (i - FEAT)];
        }
        inp[tid] = v;
    }
    __syncthreads();
    int lim = LIN1_IN - i0; if (lim > 64) lim = 64;
    float part = 0.f;
    for (int l = 0; l < lim; l++)
        part = fmaf(inp[l], l1W[(size_t)(i0 + l)*128 + tid], part);
    atomicAdd(&d_l1[tid], part);
}

__global__ void k_final2(const float* __restrict__ l4W, const float* __restrict__ l4b,
                         float* __restrict__ out) {
    __shared__ float red[4];
    int tid = threadIdx.x;
    float h = fmaxf(d_l1[tid], 0.f);
    float p = h * l4W[tid];
    #pragma unroll
    for (int o = 16; o > 0; o >>= 1) p += __shfl_xor_sync(0xffffffffu, p, o);
    if ((tid & 31) == 0) red[tid >> 5] = p;
    __syncthreads();
    if (tid == 0) out[0] = red[0] + red[1] + red[2] + red[3] + l4b[0];
}

// ---------------- launch ----------------
extern "C" void kernel_launch(void* const* d_in, const int* in_sizes, int n_in,
                              void* d_out, int out_size) {
    int iX, iEI, iW0, iB0, iW1, iB1, iW2, iB2, iC1W, iC1B, iC2W, iC2B, iW, iL1W, iL1B, iL4W, iL4B;
    if (in_sizes[0] == SN*FIN || in_sizes[0] == 2*SE) {
        if (in_sizes[0] == SN*FIN) { iX = 0; iEI = 1; } else { iX = 1; iEI = 0; }
        int b = (n_in >= 3 && in_sizes[2] == NN) ? 3 : 2;
        iW0 = b;    iB0 = b+1;  iW1 = b+2;  iB1 = b+3;  iW2 = b+4;  iB2 = b+5;
        iC1W = b+6; iC1B = b+7; iC2W = b+8; iC2B = b+9; iW = b+10;
        iL1W = b+11; iL1B = b+12; iL4W = b+13; iL4B = b+14;
    } else {
        iW0 = 0; iW1 = 1; iW2 = 2; iB0 = 3; iB1 = 4; iB2 = 5;
        iC1B = 7; iC1W = 8; iC2B = 9; iC2W = 10; iEI = 11;
        iL1W = 12; iL1B = 13; iL4W = 14; iL4B = 15; iW = 16; iX = 17;
    }

    const float* x   = (const float*)d_in[iX];
    const int*   ei  = (const int*)  d_in[iEI];
    const float* W0  = (const float*)d_in[iW0];
    const float* b0  = (const float*)d_in[iB0];
    const float* W1  = (const float*)d_in[iW1];
    const float* b1  = (const float*)d_in[iB1];
    const float* W2  = (const float*)d_in[iW2];
    const float* b2  = (const float*)d_in[iB2];
    const float* c1w = (const float*)d_in[iC1W];
    const float* c1b = (const float*)d_in[iC1B];
    const float* c2w = (const float*)d_in[iC2W];
    const float* c2b = (const float*)d_in[iC2B];
    const float* wp  = (const float*)d_in[iW];
    const float* l1W = (const float*)d_in[iL1W];
    const float* l1b = (const float*)d_in[iL1B];
    const float* l4W = (const float*)d_in[iL4W];
    const float* l4b = (const float*)d_in[iL4B];
    float* out = (float*)d_out;

    cudaFuncSetAttribute(k_topk, cudaFuncAttributeMaxDynamicSharedMemorySize, 4096*4 + 8192*8);
    cudaFuncSetAttribute(k_pool, cudaFuncAttributeMaxDynamicSharedMemorySize,
                         (16*600 + 16*300 + 16*65 + 32*16*5) * 4);

    k_init <<<(SN + 255)/256, 256>>>(l1b);
    k_deg  <<<(SE + 255)/256, 256>>>(ei);
    k_dinv <<<(SN + 255)/256, 256>>>();
    k_scanA<<<NCHUNK, 512>>>();
    k_scanB<<<1, 1024>>>();
    k_scanC<<<(SN + 255)/256, 256>>>();
    k_fill <<<(SE + 255)/256, 256>>>(ei);
    k_gemm0<<<SN/32, 256>>>(x, W0);
    k_l1   <<<SN/8, 256>>>(b0, W1);
    k_l2   <<<SN/8, 256>>>(b1, W2);
    k_l3   <<<SN/8, 256>>>(b2);
    k_topk <<<S, 1024, 4096*4 + 8192*8>>>();
    k_pool <<<S, 1024, (16*600 + 16*300 + 16*65 + 32*16*5)*4>>>(c1w, c1b, c2w, c2b);
    k_final1<<<(LIN1_IN + 63)/64, 128>>>(wp, l1W);
    k_final2<<<1, 128>>>(l4W, l4b, out);
}

// round 15
// speedup vs baseline: 1.7668x; 1.0500x over previous
#include <cuda_runtime.h>
#include <math.h>

#define S    8
#define NN   50000
#define EE   1600000
#define FIN  139
#define H    32
#define KK   600
#define LAT  65
#define C2L  296
#define DENSE (C2L*32)
#define FEAT (LAT + DENSE)
#define LIN1_IN (FEAT*2)
#define SN   (S*NN)               /* 400000 */
#define SE   (S*EE)               /* 12800000 */
#define NCHUNK ((SN + 511) / 512) /* 782 */

// ---------------- scratch ----------------
__device__ int   d_deg [SN];
__device__ float d_dinv[SN];
__device__ float d_g   [SN*H];
__device__ float d_gB  [SN*H];
__device__ float d_h1  [SN*H];
__device__ float d_h2  [SN*H];
__device__ float d_g2  [SN];
__device__ float d_h3  [SN];
__device__ int   d_off [SN];
__device__ int   d_cursor[SN];
__device__ int   d_bsum[1024];
__device__ int   d_csr [SE];
__device__ float d_feats[S*FEAT];
__device__ int   d_topk[S*KK];
__device__ float d_l1  [128];

// ---------------- init ----------------
__global__ void k_init(const float* __restrict__ l1b) {
    int i = blockIdx.x*blockDim.x + threadIdx.x;
    if (i < SN)  d_deg[i] = 1;
    if (i < 128) d_l1[i]  = l1b[i];
}

__global__ void k_deg(const int* __restrict__ ei) {
    int gid = blockIdx.x*blockDim.x + threadIdx.x;
    if (gid >= SE) return;
    int s = gid / EE, e = gid - s*EE;
    int dst = __ldg(ei + (size_t)s*2*EE + EE + e);
    atomicAdd(&d_deg[s*NN + dst], 1);
}

// ---------------- CSR build (scanA also emits dinv) ----------------
__global__ void k_scanA() {
    __shared__ int sh[512];
    int tid = threadIdx.x;
    int i = blockIdx.x*512 + tid;
    int dg = (i < SN) ? d_deg[i] : 1;
    int v = dg - 1;
    if (i < SN) d_dinv[i] = rsqrtf((float)dg);
    sh[tid] = v; __syncthreads();
    for (int o = 1; o < 512; o <<= 1) {
        int t = (tid >= o) ? sh[tid-o] : 0;
        __syncthreads(); sh[tid] += t; __syncthreads();
    }
    if (i < SN) d_off[i] = sh[tid] - v;
    if (tid == 511) d_bsum[blockIdx.x] = sh[511];
}

__global__ void k_scanB() {
    __shared__ int sh[1024];
    int tid = threadIdx.x;
    int v = (tid < NCHUNK) ? d_bsum[tid] : 0;
    sh[tid] = v; __syncthreads();
    for (int o = 1; o < 1024; o <<= 1) {
        int t = (tid >= o) ? sh[tid-o] : 0;
        __syncthreads(); sh[tid] += t; __syncthreads();
    }
    if (tid < NCHUNK) d_bsum[tid] = sh[tid] - v;
}

__global__ void k_scanC() {
    int i = blockIdx.x*blockDim.x + threadIdx.x;
    if (i >= SN) return;
    int o = d_off[i] + d_bsum[i >> 9];
    d_off[i] = o;
    d_cursor[i] = o;
}

__global__ void k_fill(const int* __restrict__ ei) {
    int gid = blockIdx.x*blockDim.x + threadIdx.x;
    if (gid >= SE) return;
    int s = gid / EE, e = gid - s*EE;
    const int* eb = ei + (size_t)s*2*EE;
    int src = __ldg(eb + e);
    int dst = __ldg(eb + EE + e);
    int pos = atomicAdd(&d_cursor[s*NN + dst], 1);
    d_csr[pos] = s*NN + src;
}

// ---------------- layer-1 GEMM (R2/R9-proven scalar version; DO NOT float4 this) ----------------
__global__ void __launch_bounds__(256) k_gemm0(const float* __restrict__ x,
                                               const float* __restrict__ W0) {
    __shared__ float W0s[FIN*H];
    __shared__ float xs[32][FIN];
    int tid = threadIdx.x;
    int g0  = blockIdx.x * 32;
    for (int i = tid; i < FIN*H; i += 256) W0s[i] = W0[i];
    const float* xg = x + (size_t)g0*FIN;
    for (int i = tid; i < 32*FIN; i += 256) { int r = i/FIN; xs[r][i - r*FIN] = xg[i]; }
    __syncthreads();
    int f = tid & 31, nb = (tid >> 5) * 4;
    float a0=0.f, a1=0.f, a2=0.f, a3=0.f;
    #pragma unroll 1
    for (int k = 0; k < FIN; k++) {
        float w = W0s[k*H + f];
        a0 = fmaf(xs[nb+0][k], w, a0);
        a1 = fmaf(xs[nb+1][k], w, a1);
        a2 = fmaf(xs[nb+2][k], w, a2);
        a3 = fmaf(xs[nb+3][k], w, a3);
    }
    int gA = g0 + nb;
    d_g[(size_t)(gA+0)*H+f] = a0 * d_dinv[gA+0];
    d_g[(size_t)(gA+1)*H+f] = a1 * d_dinv[gA+1];
    d_g[(size_t)(gA+2)*H+f] = a2 * d_dinv[gA+2];
    d_g[(size_t)(gA+3)*H+f] = a3 * d_dinv[gA+3];
}

// ---------------- shuffle-free broadcast gather (R9-proven), 8-way unrolled ----------------
__device__ __forceinline__ float gatherS(const float* __restrict__ gsrc, int n, int f) {
    int off = d_off[n];
    int end = off + d_deg[n] - 1;
    float a0 = gsrc[(size_t)n*H + f];   // self loop
    float a1 = 0.f, a2 = 0.f, a3 = 0.f;
    int e = off;
    for (; e + 8 <= end; e += 8) {
        int i0 = __ldg(d_csr + e);
        int i1 = __ldg(d_csr + e + 1);
        int i2 = __ldg(d_csr + e + 2);
        int i3 = __ldg(d_csr + e + 3);
        int i4 = __ldg(d_csr + e + 4);
        int i5 = __ldg(d_csr + e + 5);
        int i6 = __ldg(d_csr + e + 6);
        int i7 = __ldg(d_csr + e + 7);
        a0 += gsrc[(size_t)i0*H + f];
        a1 += gsrc[(size_t)i1*H + f];
        a2 += gsrc[(size_t)i2*H + f];
        a3 += gsrc[(size_t)i3*H + f];
        a0 += gsrc[(size_t)i4*H + f];
        a1 += gsrc[(size_t)i5*H + f];
        a2 += gsrc[(size_t)i6*H + f];
        a3 += gsrc[(size_t)i7*H + f];
    }
    for (; e < end; e++)
        a0 += gsrc[(size_t)__ldg(d_csr + e)*H + f];
    return (a0 + a1) + (a2 + a3);
}

// ---------------- fused: agg(g) -> h1 -> gB ----------------
__global__ void __launch_bounds__(256) k_l1(const float* __restrict__ b0,
                                            const float* __restrict__ W1) {
    __shared__ float W1s[H*H];
    int tid = threadIdx.x;
    for (int i = tid; i < H*H; i += 256) W1s[i] = W1[i];
    __syncthreads();
    int n = blockIdx.x*8 + (tid >> 5);
    int f = tid & 31;
    float acc = gatherS(d_g, n, f);
    float dv = d_dinv[n];
    float h = tanhf(acc*dv + __ldg(b0 + f));
    d_h1[(size_t)n*H + f] = h;
    float v = 0.f;
    #pragma unroll
    for (int k = 0; k < H; k++)
        v = fmaf(__shfl_sync(0xffffffffu, h, k), W1s[k*H + f], v);
    d_gB[(size_t)n*H + f] = v * dv;
}

// ---------------- fused: agg(gB) -> h2 -> g2 ----------------
__global__ void __launch_bounds__(256) k_l2(const float* __restrict__ b1,
                                            const float* __restrict__ W2) {
    int tid = threadIdx.x;
    int n = blockIdx.x*8 + (tid >> 5);
    int f = tid & 31;
    float acc = gatherS(d_gB, n, f);
    float dv = d_dinv[n];
    float h = tanhf(acc*dv + __ldg(b1 + f));
    d_h2[(size_t)n*H + f] = h;
    float p = h * __ldg(W2 + f);
    #pragma unroll
    for (int o = 16; o > 0; o >>= 1) p += __shfl_xor_sync(0xffffffffu, p, o);
    if (f == 0) d_g2[n] = p * dv;
}

// ---------------- fused: scalar agg(g2) -> h3 ----------------
__global__ void __launch_bounds__(256) k_l3(const float* __restrict__ b2) {
    int tid = threadIdx.x;
    int n = blockIdx.x*8 + (tid >> 5);
    int lane = tid & 31;
    int off = d_off[n];
    int cnt = d_deg[n] - 1;
    float a = 0.f;
    for (int e = lane; e < cnt; e += 32) a += d_g2[d_csr[off + e]];
    #pragma unroll
    for (int o = 16; o > 0; o >>= 1) a += __shfl_xor_sync(0xffffffffu, a, o);
    if (lane == 0)
        d_h3[n] = tanhf((d_g2[n] + a) * d_dinv[n] + __ldg(b2));
}

// ---------------- exact stable top-600 per snapshot ----------------
__device__ __forceinline__ unsigned mono_f(float v) {
    unsigned u = __float_as_uint(v);
    return (u & 0x80000000u) ? ~u : (u | 0x80000000u);
}

__global__ void k_topk() {
    extern __shared__ unsigned char smraw[];
    int* hist = (int*)smraw;
    unsigned long long* cand = (unsigned long long*)(smraw + 4096*4);
    __shared__ int sB1, sPre, sB2, sCnt;
    int s = blockIdx.x, tid = threadIdx.x;
    const float* key = d_h3 + s*NN;

    for (int i = tid; i < 4096; i += 1024) hist[i] = 0;
    __syncthreads();
    for (int n = tid; n < NN; n += 1024)
        atomicAdd(&hist[mono_f(key[n]) >> 20], 1);
    __syncthreads();
    if (tid == 0) {
        int cum = 0, b = 4095;
        for (; b >= 0; b--) { cum += hist[b]; if (cum >= KK) break; }
        sB1 = b; sPre = cum - hist[b];
    }
    __syncthreads();
    int B1 = sB1, pre1 = sPre;
    for (int i = tid; i < 4096; i += 1024) hist[i] = 0;
    __syncthreads();
    for (int n = tid; n < NN; n += 1024) {
        unsigned u = mono_f(key[n]);
        if ((int)(u >> 20) == B1) atomicAdd(&hist[(u >> 8) & 0xFFF], 1);
    }
    __syncthreads();
    if (tid == 0) {
        int cum = pre1, b = 4095;
        for (; b >= 0; b--) { cum += hist[b]; if (cum >= KK) break; }
        sB2 = b; sCnt = 0;
    }
    __syncthreads();
    unsigned T = ((unsigned)B1 << 12) | (unsigned)sB2;
    for (int n = tid; n < NN; n += 1024) {
        unsigned u = mono_f(key[n]);
        if ((u >> 8) >= T) {
            int p = atomicAdd(&sCnt, 1);
            if (p < 8192)
                cand[p] = ((unsigned long long)u << 32) | (unsigned)(0xFFFFFFFFu - n);
        }
    }
    __syncthreads();
    int cnt = sCnt < 8192 ? sCnt : 8192;
    int m = 1024;
    while (m < cnt) m <<= 1;
    for (int i = tid; i < m; i += 1024) if (i >= cnt) cand[i] = 0ull;
    __syncthreads();
    for (int k = 2; k <= m; k <<= 1) {
        for (int j = k >> 1; j > 0; j >>= 1) {
            for (int t = tid; t < m; t += 1024) {
                int ixj = t ^ j;
                if (ixj > t) {
                    unsigned long long a = cand[t], b = cand[ixj];
                    bool up = ((t & k) == 0);
                    if (up ? (a < b) : (a > b)) { cand[t] = b; cand[ixj] = a; }
                }
            }
            __syncthreads();
        }
    }
    for (int j = tid; j < KK; j += 1024)
        d_topk[s*KK + j] = (int)(0xFFFFFFFFu - (unsigned)(cand[j] & 0xFFFFFFFFu));
}

// ---------------- sort-pool convs + emb_edge ----------------
__global__ void k_pool(const float* __restrict__ c1w, const float* __restrict__ c1b,
                       const float* __restrict__ c2w, const float* __restrict__ c2b) {
    extern __shared__ float smf[];
    float* z1  = smf;
    float* zp  = z1 + 16*600;
    float* w1s = zp + 16*300;
    float* w2s = w1s + 16*65;
    int s = blockIdx.x, tid = threadIdx.x;
    for (int i = tid; i < 16*65;   i += 1024) w1s[i] = c1w[i];
    for (int i = tid; i < 32*16*5; i += 1024) w2s[i] = c2w[i];
    __syncthreads();
    for (int p = tid; p < 16*600; p += 1024) {
        int c = p / 600, j = p - c*600;
        int n = d_topk[s*KK + j];
        int base = s*NN + n;
        const float* w  = w1s + c*65;
        const float* r1 = d_h1 + (size_t)base*H;
        const float* r2 = d_h2 + (size_t)base*H;
        float a = __ldg(c1b + c);
        #pragma unroll 8
        for (int t = 0; t < 32; t++) a = fmaf(w[t],    r1[t], a);
        #pragma unroll 8
        for (int t = 0; t < 32; t++) a = fmaf(w[32+t], r2[t], a);
        a = fmaf(w[64], d_h3[base], a);
        z1[c*600 + j] = fmaxf(a, 0.f);
    }
    __syncthreads();
    for (int p = tid; p < 16*300; p += 1024) {
        int c = p / 300, j = p - c*300;
        zp[c*300 + j] = fmaxf(z1[c*600 + 2*j], z1[c*600 + 2*j + 1]);
    }
    __syncthreads();
    float* out = d_feats + s*FEAT;
    for (int p = tid; p < 32*C2L; p += 1024) {
        int o = p / C2L, j = p - o*C2L;
        float a = __ldg(c2b + o);
        #pragma unroll
        for (int i = 0; i < 16; i++) {
            const float* w = w2s + (o*16 + i)*5;
            const float* z = zp + i*300 + j;
            #pragma unroll
            for (int t = 0; t < 5; t++) a = fmaf(w[t], z[t], a);
        }
        out[LAT + p] = fmaxf(a, 0.f);
    }
    for (int t = tid; t < LAT; t += 1024) {
        int b0i = s*NN, b1i = s*NN + 1;
        float v0 = (t < 32) ? d_h1[(size_t)b0i*H + t] : (t < 64) ? d_h2[(size_t)b0i*H + (t-32)] : d_h3[b0i];
        float v1 = (t < 32) ? d_h1[(size_t)b1i*H + t] : (t < 64) ? d_h2[(size_t)b1i*H + (t-32)] : d_h3[b1i];
        out[t] = v0 * v1;
    }
}

// ---------------- temporal combine + lin1 GEMV ----------------
__global__ void __launch_bounds__(128) k_final1(const float* __restrict__ wp,
                                                const float* __restrict__ l1W) {
    __shared__ float inp[64];
    int tid = threadIdx.x, i0 = blockIdx.x*64;
    float om = 1.0f - *wp;
    if (tid < 64) {
        int i = i0 + tid; float v = 0.f;
        if (i < LIN1_IN) {
            if (i < FEAT) {
                v = d_feats[6*FEAT + i];
                float coef = 1.f;
                for (int t = 5; t >= 0; t--) { v = fmaf(coef, d_feats[t*FEAT + i], v); coef *= om; }
            } else v = d_feats[7*FEAT + (i - FEAT)];
        }
        inp[tid] = v;
    }
    __syncthreads();
    int lim = LIN1_IN - i0; if (lim > 64) lim = 64;
    float part = 0.f;
    for (int l = 0; l < lim; l++)
        part = fmaf(inp[l], l1W[(size_t)(i0 + l)*128 + tid], part);
    atomicAdd(&d_l1[tid], part);
}

__global__ void k_final2(const float* __restrict__ l4W, const float* __restrict__ l4b,
                         float* __restrict__ out) {
    __shared__ float red[4];
    int tid = threadIdx.x;
    float h = fmaxf(d_l1[tid], 0.f);
    float p = h * l4W[tid];
    #pragma unroll
    for (int o = 16; o > 0; o >>= 1) p += __shfl_xor_sync(0xffffffffu, p, o);
    if ((tid & 31) == 0) red[tid >> 5] = p;
    __syncthreads();
    if (tid == 0) out[0] = red[0] + red[1] + red[2] + red[3] + l4b[0];
}

// ---------------- launch ----------------
extern "C" void kernel_launch(void* const* d_in, const int* in_sizes, int n_in,
                              void* d_out, int out_size) {
    int iX, iEI, iW0, iB0, iW1, iB1, iW2, iB2, iC1W, iC1B, iC2W, iC2B, iW, iL1W, iL1B, iL4W, iL4B;
    if (in_sizes[0] == SN*FIN || in_sizes[0] == 2*SE) {
        if (in_sizes[0] == SN*FIN) { iX = 0; iEI = 1; } else { iX = 1; iEI = 0; }
        int b = (n_in >= 3 && in_sizes[2] == NN) ? 3 : 2;
        iW0 = b;    iB0 = b+1;  iW1 = b+2;  iB1 = b+3;  iW2 = b+4;  iB2 = b+5;
        iC1W = b+6; iC1B = b+7; iC2W = b+8; iC2B = b+9; iW = b+10;
        iL1W = b+11; iL1B = b+12; iL4W = b+13; iL4B = b+14;
    } else {
        iW0 = 0; iW1 = 1; iW2 = 2; iB0 = 3; iB1 = 4; iB2 = 5;
        iC1B = 7; iC1W = 8; iC2B = 9; iC2W = 10; iEI = 11;
        iL1W = 12; iL1B = 13; iL4W = 14; iL4B = 15; iW = 16; iX = 17;
    }

    const float* x   = (const float*)d_in[iX];
    const int*   ei  = (const int*)  d_in[iEI];
    const float* W0  = (const float*)d_in[iW0];
    const float* b0  = (const float*)d_in[iB0];
    const float* W1  = (const float*)d_in[iW1];
    const float* b1  = (const float*)d_in[iB1];
    const float* W2  = (const float*)d_in[iW2];
    const float* b2  = (const float*)d_in[iB2];
    const float* c1w = (const float*)d_in[iC1W];
    const float* c1b = (const float*)d_in[iC1B];
    const float* c2w = (const float*)d_in[iC2W];
    const float* c2b = (const float*)d_in[iC2B];
    const float* wp  = (const float*)d_in[iW];
    const float* l1W = (const float*)d_in[iL1W];
    const float* l1b = (const float*)d_in[iL1B];
    const float* l4W = (const float*)d_in[iL4W];
    const float* l4b = (const float*)d_in[iL4B];
    float* out = (float*)d_out;

    cudaFuncSetAttribute(k_topk, cudaFuncAttributeMaxDynamicSharedMemorySize, 4096*4 + 8192*8);
    cudaFuncSetAttribute(k_pool, cudaFuncAttributeMaxDynamicSharedMemorySize,
                         (16*600 + 16*300 + 16*65 + 32*16*5) * 4);

    k_init <<<(SN + 255)/256, 256>>>(l1b);
    k_deg  <<<(SE + 255)/256, 256>>>(ei);
    k_scanA<<<NCHUNK, 512>>>();
    k_scanB<<<1, 1024>>>();
    k_scanC<<<(SN + 255)/256, 256>>>();
    k_fill <<<(SE + 255)/256, 256>>>(ei);
    k_gemm0<<<SN/32, 256>>>(x, W0);
    k_l1   <<<SN/8, 256>>>(b0, W1);
    k_l2   <<<SN/8, 256>>>(b1, W2);
    k_l3   <<<SN/8, 256>>>(b2);
    k_topk <<<S, 1024, 4096*4 + 8192*8>>>();
    k_pool <<<S, 1024, (16*600 + 16*300 + 16*65 + 32*16*5)*4>>>(c1w, c1b, c2w, c2b);
    k_final1<<<(LIN1_IN + 63)/64, 128>>>(wp, l1W);
    k_final2<<<1, 128>>>(l4W, l4b, out);
}

// round 17
// speedup vs baseline: 1.8153x; 1.0275x over previous
#include <cuda_runtime.h>
#include <math.h>

#define S    8
#define NN   50000
#define EE   1600000
#define FIN  139
#define H    32
#define KK   600
#define LAT  65
#define C2L  296
#define DENSE (C2L*32)
#define FEAT (LAT + DENSE)
#define LIN1_IN (FEAT*2)
#define SN   (S*NN)               /* 400000 */
#define SE   (S*EE)               /* 12800000 */
#define NCHUNK ((SN + 511) / 512) /* 782 */
#define CSRCAP (SE + 8*SN)        /* padded CSR capacity */

// ---------------- scratch ----------------
__device__ int   d_deg [SN];
__device__ float d_dinv[SN];
__device__ float d_g   [(SN+1)*H];   // +1: zero row for padded dummy edges
__device__ float d_gB  [(SN+1)*H];
__device__ float d_h1  [SN*H];
__device__ float d_h2  [SN*H];
__device__ float d_g2  [SN];
__device__ float d_h3  [SN];
__device__ int   d_off [SN];
__device__ int   d_cursor[SN];
__device__ int   d_bsum[1024];
__device__ int   d_csr [CSRCAP];
__device__ float d_feats[S*FEAT];
__device__ int   d_topk[S*KK];
__device__ float d_l1  [128];

// ---------------- init ----------------
__global__ void k_init(const float* __restrict__ l1b) {
    int i = blockIdx.x*blockDim.x + threadIdx.x;
    if (i < SN)  d_deg[i] = 1;
    if (i < 128) d_l1[i]  = l1b[i];
    if (i < H) { d_g[(size_t)SN*H + i] = 0.f; d_gB[(size_t)SN*H + i] = 0.f; }
}

__global__ void k_deg(const int* __restrict__ ei) {
    int gid = blockIdx.x*blockDim.x + threadIdx.x;
    if (gid >= SE) return;
    int s = gid / EE, e = gid - s*EE;
    int dst = __ldg(ei + (size_t)s*2*EE + EE + e);
    atomicAdd(&d_deg[s*NN + dst], 1);
}

// ---------------- CSR build (padded to 8; scanA also emits dinv) ----------------
__global__ void k_scanA() {
    __shared__ int sh[512];
    int tid = threadIdx.x;
    int i = blockIdx.x*512 + tid;
    int dg = (i < SN) ? d_deg[i] : 1;
    int v = ((dg - 1) + 7) & ~7;          // padded adjacency length
    if (i < SN) d_dinv[i] = rsqrtf((float)dg);
    sh[tid] = v; __syncthreads();
    for (int o = 1; o < 512; o <<= 1) {
        int t = (tid >= o) ? sh[tid-o] : 0;
        __syncthreads(); sh[tid] += t; __syncthreads();
    }
    if (i < SN) d_off[i] = sh[tid] - v;
    if (tid == 511) d_bsum[blockIdx.x] = sh[511];
}

__global__ void k_scanB() {
    __shared__ int sh[1024];
    int tid = threadIdx.x;
    int v = (tid < NCHUNK) ? d_bsum[tid] : 0;
    sh[tid] = v; __syncthreads();
    for (int o = 1; o < 1024; o <<= 1) {
        int t = (tid >= o) ? sh[tid-o] : 0;
        __syncthreads(); sh[tid] += t; __syncthreads();
    }
    if (tid < NCHUNK) d_bsum[tid] = sh[tid] - v;
}

__global__ void k_scanC() {
    int i = blockIdx.x*blockDim.x + threadIdx.x;
    if (i >= SN) return;
    int o = d_off[i] + d_bsum[i >> 9];
    d_off[i] = o;
    d_cursor[i] = o;
}

__global__ void k_fill(const int* __restrict__ ei) {
    int gid = blockIdx.x*blockDim.x + threadIdx.x;
    if (gid >= SE) return;
    int s = gid / EE, e = gid - s*EE;
    const int* eb = ei + (size_t)s*2*EE;
    int src = __ldg(eb + e);
    int dst = __ldg(eb + EE + e);
    int pos = atomicAdd(&d_cursor[s*NN + dst], 1);
    d_csr[pos] = s*NN + src;
}

// fill padding tail slots with dummy index SN (zero feature row)
__global__ void k_pad() {
    int n = blockIdx.x*blockDim.x + threadIdx.x;
    if (n >= SN) return;
    int cnt = d_deg[n] - 1;
    int pc  = (cnt + 7) & ~7;
    int off = d_off[n];
    for (int p = off + cnt; p < off + pc; p++) d_csr[p] = SN;
}

// ---------------- layer-1 GEMM (proven scalar version; unroll widened only) ----------------
__global__ void __launch_bounds__(256) k_gemm0(const float* __restrict__ x,
                                               const float* __restrict__ W0) {
    __shared__ float W0s[FIN*H];
    __shared__ float xs[32][FIN];
    int tid = threadIdx.x;
    int g0  = blockIdx.x * 32;
    for (int i = tid; i < FIN*H; i += 256) W0s[i] = W0[i];
    const float* xg = x + (size_t)g0*FIN;
    for (int i = tid; i < 32*FIN; i += 256) { int r = i/FIN; xs[r][i - r*FIN] = xg[i]; }
    __syncthreads();
    int f = tid & 31, nb = (tid >> 5) * 4;
    float a0=0.f, a1=0.f, a2=0.f, a3=0.f;
    #pragma unroll 4
    for (int k = 0; k < FIN; k++) {
        float w = W0s[k*H + f];
        a0 = fmaf(xs[nb+0][k], w, a0);
        a1 = fmaf(xs[nb+1][k], w, a1);
        a2 = fmaf(xs[nb+2][k], w, a2);
        a3 = fmaf(xs[nb+3][k], w, a3);
    }
    int gA = g0 + nb;
    d_g[(size_t)(gA+0)*H+f] = a0 * d_dinv[gA+0];
    d_g[(size_t)(gA+1)*H+f] = a1 * d_dinv[gA+1];
    d_g[(size_t)(gA+2)*H+f] = a2 * d_dinv[gA+2];
    d_g[(size_t)(gA+3)*H+f] = a3 * d_dinv[gA+3];
}

// ---------------- shuffle-free broadcast gather on padded CSR (int4 index loads) ----------------
__device__ __forceinline__ float gatherP(const float* __restrict__ gsrc, int n, int f) {
    int off = d_off[n];                         // multiple of 8 -> 32B aligned
    int pc  = (d_deg[n] - 1 + 7) & ~7;
    float a0 = gsrc[(size_t)n*H + f];           // self loop
    float a1 = 0.f, a2 = 0.f, a3 = 0.f;
    const int4* cp = (const int4*)(d_csr + off);
    for (int e = 0; e < pc; e += 8) {
        int4 A = __ldg(cp);
        int4 B = __ldg(cp + 1);
        cp += 2;
        a0 += gsrc[(size_t)A.x*H + f];
        a1 += gsrc[(size_t)A.y*H + f];
        a2 += gsrc[(size_t)A.z*H + f];
        a3 += gsrc[(size_t)A.w*H + f];
        a0 += gsrc[(size_t)B.x*H + f];
        a1 += gsrc[(size_t)B.y*H + f];
        a2 += gsrc[(size_t)B.z*H + f];
        a3 += gsrc[(size_t)B.w*H + f];
    }
    return (a0 + a1) + (a2 + a3);
}

// ---------------- fused: agg(g) -> h1 -> gB ----------------
__global__ void __launch_bounds__(256) k_l1(const float* __restrict__ b0,
                                            const float* __restrict__ W1) {
    __shared__ float W1s[H*H];
    int tid = threadIdx.x;
    for (int i = tid; i < H*H; i += 256) W1s[i] = W1[i];
    __syncthreads();
    int n = blockIdx.x*8 + (tid >> 5);
    int f = tid & 31;
    float acc = gatherP(d_g, n, f);
    float dv = d_dinv[n];
    float h = tanhf(acc*dv + __ldg(b0 + f));
    d_h1[(size_t)n*H + f] = h;
    float v = 0.f;
    #pragma unroll
    for (int k = 0; k < H; k++)
        v = fmaf(__shfl_sync(0xffffffffu, h, k), W1s[k*H + f], v);
    d_gB[(size_t)n*H + f] = v * dv;
}

// ---------------- fused: agg(gB) -> h2 -> g2 ----------------
__global__ void __launch_bounds__(256) k_l2(const float* __restrict__ b1,
                                            const float* __restrict__ W2) {
    int tid = threadIdx.x;
    int n = blockIdx.x*8 + (tid >> 5);
    int f = tid & 31;
    float acc = gatherP(d_gB, n, f);
    float dv = d_dinv[n];
    float h = tanhf(acc*dv + __ldg(b1 + f));
    d_h2[(size_t)n*H + f] = h;
    float p = h * __ldg(W2 + f);
    #pragma unroll
    for (int o = 16; o > 0; o >>= 1) p += __shfl_xor_sync(0xffffffffu, p, o);
    if (f == 0) d_g2[n] = p * dv;
}

// ---------------- fused: scalar agg(g2) -> h3 (exact-count loop; real edges first) ----------------
__global__ void __launch_bounds__(256) k_l3(const float* __restrict__ b2) {
    int tid = threadIdx.x;
    int n = blockIdx.x*8 + (tid >> 5);
    int lane = tid & 31;
    int off = d_off[n];
    int cnt = d_deg[n] - 1;
    float a = 0.f;
    for (int e = lane; e < cnt; e += 32) a += d_g2[d_csr[off + e]];
    #pragma unroll
    for (int o = 16; o > 0; o >>= 1) a += __shfl_xor_sync(0xffffffffu, a, o);
    if (lane == 0)
        d_h3[n] = tanhf((d_g2[n] + a) * d_dinv[n] + __ldg(b2));
}

// ---------------- exact stable top-600 per snapshot ----------------
__device__ __forceinline__ unsigned mono_f(float v) {
    unsigned u = __float_as_uint(v);
    return (u & 0x80000000u) ? ~u : (u | 0x80000000u);
}

__global__ void k_topk() {
    extern __shared__ unsigned char smraw[];
    int* hist = (int*)smraw;
    unsigned long long* cand = (unsigned long long*)(smraw + 4096*4);
    __shared__ int sB1, sPre, sB2, sCnt;
    int s = blockIdx.x, tid = threadIdx.x;
    const float* key = d_h3 + s*NN;

    for (int i = tid; i < 4096; i += 1024) hist[i] = 0;
    __syncthreads();
    for (int n = tid; n < NN; n += 1024)
        atomicAdd(&hist[mono_f(key[n]) >> 20], 1);
    __syncthreads();
    if (tid == 0) {
        int cum = 0, b = 4095;
        for (; b >= 0; b--) { cum += hist[b]; if (cum >= KK) break; }
        sB1 = b; sPre = cum - hist[b];
    }
    __syncthreads();
    int B1 = sB1, pre1 = sPre;
    for (int i = tid; i < 4096; i += 1024) hist[i] = 0;
    __syncthreads();
    for (int n = tid; n < NN; n += 1024) {
        unsigned u = mono_f(key[n]);
        if ((int)(u >> 20) == B1) atomicAdd(&hist[(u >> 8) & 0xFFF], 1);
    }
    __syncthreads();
    if (tid == 0) {
        int cum = pre1, b = 4095;
        for (; b >= 0; b--) { cum += hist[b]; if (cum >= KK) break; }
        sB2 = b; sCnt = 0;
    }
    __syncthreads();
    unsigned T = ((unsigned)B1 << 12) | (unsigned)sB2;
    for (int n = tid; n < NN; n += 1024) {
        unsigned u = mono_f(key[n]);
        if ((u >> 8) >= T) {
            int p = atomicAdd(&sCnt, 1);
            if (p < 8192)
                cand[p] = ((unsigned long long)u << 32) | (unsigned)(0xFFFFFFFFu - n);
        }
    }
    __syncthreads();
    int cnt = sCnt < 8192 ? sCnt : 8192;
    int m = 1024;
    while (m < cnt) m <<= 1;
    for (int i = tid; i < m; i += 1024) if (i >= cnt) cand[i] = 0ull;
    __syncthreads();
    for (int k = 2; k <= m; k <<= 1) {
        for (int j = k >> 1; j > 0; j >>= 1) {
            for (int t = tid; t < m; t += 1024) {
                int ixj = t ^ j;
                if (ixj > t) {
                    unsigned long long a = cand[t], b = cand[ixj];
                    bool up = ((t & k) == 0);
                    if (up ? (a < b) : (a > b)) { cand[t] = b; cand[ixj] = a; }
                }
            }
            __syncthreads();
        }
    }
    for (int j = tid; j < KK; j += 1024)
        d_topk[s*KK + j] = (int)(0xFFFFFFFFu - (unsigned)(cand[j] & 0xFFFFFFFFu));
}

// ---------------- sort-pool convs + emb_edge ----------------
__global__ void k_pool(const float* __restrict__ c1w, const float* __restrict__ c1b,
                       const float* __restrict__ c2w, const float* __restrict__ c2b) {
    extern __shared__ float smf[];
    float* z1  = smf;
    float* zp  = z1 + 16*600;
    float* w1s = zp + 16*300;
    float* w2s = w1s + 16*65;
    int s = blockIdx.x, tid = threadIdx.x;
    for (int i = tid; i < 16*65;   i += 1024) w1s[i] = c1w[i];
    for (int i = tid; i < 32*16*5; i += 1024) w2s[i] = c2w[i];
    __syncthreads();
    for (int p = tid; p < 16*600; p += 1024) {
        int c = p / 600, j = p - c*600;
        int n = d_topk[s*KK + j];
        int base = s*NN + n;
        const float* w  = w1s + c*65;
        const float* r1 = d_h1 + (size_t)base*H;
        const float* r2 = d_h2 + (size_t)base*H;
        float a = __ldg(c1b + c);
        #pragma unroll 8
        for (int t = 0; t < 32; t++) a = fmaf(w[t],    r1[t], a);
        #pragma unroll 8
        for (int t = 0; t < 32; t++) a = fmaf(w[32+t], r2[t], a);
        a = fmaf(w[64], d_h3[base], a);
        z1[c*600 + j] = fmaxf(a, 0.f);
    }
    __syncthreads();
    for (int p = tid; p < 16*300; p += 1024) {
        int c = p / 300, j = p - c*300;
        zp[c*300 + j] = fmaxf(z1[c*600 + 2*j], z1[c*600 + 2*j + 1]);
    }
    __syncthreads();
    float* out = d_feats + s*FEAT;
    for (int p = tid; p < 32*C2L; p += 1024) {
        int o = p / C2L, j = p - o*C2L;
        float a = __ldg(c2b + o);
        #pragma unroll
        for (int i = 0; i < 16; i++) {
            const float* w = w2s + (o*16 + i)*5;
            const float* z = zp + i*300 + j;
            #pragma unroll
            for (int t = 0; t < 5; t++) a = fmaf(w[t], z[t], a);
        }
        out[LAT + p] = fmaxf(a, 0.f);
    }
    for (int t = tid; t < LAT; t += 1024) {
        int b0i = s*NN, b1i = s*NN + 1;
        float v0 = (t < 32) ? d_h1[(size_t)b0i*H + t] : (t < 64) ? d_h2[(size_t)b0i*H + (t-32)] : d_h3[b0i];
        float v1 = (t < 32) ? d_h1[(size_t)b1i*H + t] : (t < 64) ? d_h2[(size_t)b1i*H + (t-32)] : d_h3[b1i];
        out[t] = v0 * v1;
    }
}

// ---------------- temporal combine + lin1 GEMV ----------------
__global__ void __launch_bounds__(128) k_final1(const float* __restrict__ wp,
                                                const float* __restrict__ l1W) {
    __shared__ float inp[64];
    int tid = threadIdx.x, i0 = blockIdx.x*64;
    float om = 1.0f - *wp;
    if (tid < 64) {
        int i = i0 + tid; float v = 0.f;
        if (i < LIN1_IN) {
            if (i < FEAT) {
                v = d_feats[6*FEAT + i];
                float coef = 1.f;
                for (int t = 5; t >= 0; t--) { v = fmaf(coef, d_feats[t*FEAT + i], v); coef *= om; }
            } else v = d_feats[7*FEAT + (i - FEAT)];
        }
        inp[tid] = v;
    }
    __syncthreads();
    int lim = LIN1_IN - i0; if (lim > 64) lim = 64;
    float part = 0.f;
    for (int l = 0; l < lim; l++)
        part = fmaf(inp[l], l1W[(size_t)(i0 + l)*128 + tid], part);
    atomicAdd(&d_l1[tid], part);
}

__global__ void k_final2(const float* __restrict__ l4W, const float* __restrict__ l4b,
                         float* __restrict__ out) {
    __shared__ float red[4];
    int tid = threadIdx.x;
    float h = fmaxf(d_l1[tid], 0.f);
    float p = h * l4W[tid];
    #pragma unroll
    for (int o = 16; o > 0; o >>= 1) p += __shfl_xor_sync(0xffffffffu, p, o);
    if ((tid & 31) == 0) red[tid >> 5] = p;
    __syncthreads();
    if (tid == 0) out[0] = red[0] + red[1] + red[2] + red[3] + l4b[0];
}

// ---------------- launch ----------------
extern "C" void kernel_launch(void* const* d_in, const int* in_sizes, int n_in,
                              void* d_out, int out_size) {
    int iX, iEI, iW0, iB0, iW1, iB1, iW2, iB2, iC1W, iC1B, iC2W, iC2B, iW, iL1W, iL1B, iL4W, iL4B;
    if (in_sizes[0] == SN*FIN || in_sizes[0] == 2*SE) {
        if (in_sizes[0] == SN*FIN) { iX = 0; iEI = 1; } else { iX = 1; iEI = 0; }
        int b = (n_in >= 3 && in_sizes[2] == NN) ? 3 : 2;
        iW0 = b;    iB0 = b+1;  iW1 = b+2;  iB1 = b+3;  iW2 = b+4;  iB2 = b+5;
        iC1W = b+6; iC1B = b+7; iC2W = b+8; iC2B = b+9; iW = b+10;
        iL1W = b+11; iL1B = b+12; iL4W = b+13; iL4B = b+14;
    } else {
        iW0 = 0; iW1 = 1; iW2 = 2; iB0 = 3; iB1 = 4; iB2 = 5;
        iC1B = 7; iC1W = 8; iC2B = 9; iC2W = 10; iEI = 11;
        iL1W = 12; iL1B = 13; iL4W = 14; iL4B = 15; iW = 16; iX = 17;
    }

    const float* x   = (const float*)d_in[iX];
    const int*   ei  = (const int*)  d_in[iEI];
    const float* W0  = (const float*)d_in[iW0];
    const float* b0  = (const float*)d_in[iB0];
    const float* W1  = (const float*)d_in[iW1];
    const float* b1  = (const float*)d_in[iB1];
    const float* W2  = (const float*)d_in[iW2];
    const float* b2  = (const float*)d_in[iB2];
    const float* c1w = (const float*)d_in[iC1W];
    const float* c1b = (const float*)d_in[iC1B];
    const float* c2w = (const float*)d_in[iC2W];
    const float* c2b = (const float*)d_in[iC2B];
    const float* wp  = (const float*)d_in[iW];
    const float* l1W = (const float*)d_in[iL1W];
    const float* l1b = (const float*)d_in[iL1B];
    const float* l4W = (const float*)d_in[iL4W];
    const float* l4b = (const float*)d_in[iL4B];
    float* out = (float*)d_out;

    cudaFuncSetAttribute(k_topk, cudaFuncAttributeMaxDynamicSharedMemorySize, 4096*4 + 8192*8);
    cudaFuncSetAttribute(k_pool, cudaFuncAttributeMaxDynamicSharedMemorySize,
                         (16*600 + 16*300 + 16*65 + 32*16*5) * 4);

    k_init <<<(SN + 255)/256, 256>>>(l1b);
    k_deg  <<<(SE + 255)/256, 256>>>(ei);
    k_scanA<<<NCHUNK, 512>>>();
    k_scanB<<<1, 1024>>>();
    k_scanC<<<(SN + 255)/256, 256>>>();
    k_fill <<<(SE + 255)/256, 256>>>(ei);
    k_pad  <<<(SN + 255)/256, 256>>>();
    k_gemm0<<<SN/32, 256>>>(x, W0);
    k_l1   <<<SN/8, 256>>>(b0, W1);
    k_l2   <<<SN/8, 256>>>(b1, W2);
    k_l3   <<<SN/8, 256>>>(b2);
    k_topk <<<S, 1024, 4096*4 + 8192*8>>>();
    k_pool <<<S, 1024, (16*600 + 16*300 + 16*65 + 32*16*5)*4>>>(c1w, c1b, c2w, c2b);
    k_final1<<<(LIN1_IN + 63)/64, 128>>>(wp, l1W);
    k_final2<<<1, 128>>>(l4W, l4b, out);
}